// round 14
// baseline (speedup 1.0000x reference)
#include <cuda_runtime.h>
#include <cuda_fp16.h>
#include <math_constants.h>
#include <cstdint>

// Problem constants
#define K_CODES 8192
#define DIM     256
#define TLEN    2048
#define BATCH   16
#define NTOK    32768           // BATCH*TLEN

// Output layout (float32, concatenated in reference-return order)
#define OFF_ZQ    0ull
#define OFF_IDX   8388608ull
#define OFF_LOSS  8421376ull
#define OFF_NEMB  8421377ull
#define OFF_NCS   10518529ull
#define OFF_NEA   10526721ull
#define OFF_UTIL  12623873ull

#define MARGIN 0.15f

// Scratch (device globals; no allocation allowed). uint4 for 16B alignment.
__device__ float g_esq[K_CODES];
__device__ int   g_idx[NTOK];
__device__ float g_counts[K_CODES];
__device__ float g_sumemb[K_CODES * DIM];
__device__ float g_scal[4];   // [0]=loss partial sum, [1]=n
__device__ int   g_nfix;
__device__ int   g_fixlist[NTOK];
__device__ float g_pv[NTOK * 4];            // rescore partial min value per quarter
__device__ int   g_pi[NTOK * 4];            // rescore partial min index per quarter
__device__ uint4 g_z1u[NTOK * DIM / 8];     // fp16 z, (token, dim)
__device__ uint4 g_e1u[K_CODES * DIM / 8];  // fp16 codebook, (code, dim)

// ===========================================================================
// PTX helpers (plain sm_80+ features — tcgen05 unavailable on compute_100)
// ===========================================================================
__device__ __forceinline__ uint32_t smem_to_u32(const void* smem_ptr) {
    uint32_t addr;
    asm("{ .reg .u64 tmp; cvta.to.shared.u64 tmp, %1; cvt.u32.u64 %0, tmp; }"
        : "=r"(addr) : "l"(smem_ptr));
    return addr;
}

#define CP_ASYNC16(dst, src) \
    asm volatile("cp.async.cg.shared.global [%0], [%1], 16;" :: "r"(dst), "l"(src) : "memory")
#define CP_COMMIT() asm volatile("cp.async.commit_group;" ::: "memory")
#define CP_WAIT1()  asm volatile("cp.async.wait_group 1;" ::: "memory")
#define CP_WAIT0()  asm volatile("cp.async.wait_group 0;" ::: "memory")

__device__ __forceinline__ void ldsm_x4(uint32_t* r, uint32_t addr) {
    asm volatile("ldmatrix.sync.aligned.m8n8.x4.shared.b16 {%0,%1,%2,%3}, [%4];"
        : "=r"(r[0]), "=r"(r[1]), "=r"(r[2]), "=r"(r[3]) : "r"(addr));
}

__device__ __forceinline__ void mma_16816(float* c, const uint32_t* a, const uint32_t* b) {
    asm volatile(
        "mma.sync.aligned.m16n8k16.row.col.f32.f16.f16.f32 "
        "{%0,%1,%2,%3}, {%4,%5,%6,%7}, {%8,%9}, {%0,%1,%2,%3};"
        : "+f"(c[0]), "+f"(c[1]), "+f"(c[2]), "+f"(c[3])
        : "r"(a[0]), "r"(a[1]), "r"(a[2]), "r"(a[3]), "r"(b[0]), "r"(b[1]));
}

// ===========================================================================
// Fused zero-scratch + esq + codebook fp16 prep. grid 1024 x 256.
// ===========================================================================
__global__ void k_init_esq_prep(const float* __restrict__ emb) {
    int gid  = blockIdx.x * blockDim.x + threadIdx.x;   // 0..262143
    int warp = gid >> 5;                                // 0..8191
    int lane = threadIdx.x & 31;
    ((float4*)g_sumemb)[gid] = make_float4(0.f, 0.f, 0.f, 0.f);
    ((float4*)g_sumemb)[gid + 262144] = make_float4(0.f, 0.f, 0.f, 0.f);
    if (gid < K_CODES) g_counts[gid] = 0.f;
    if (gid < 4) g_scal[gid] = 0.f;
    if (gid == 0) g_nfix = 0;
    // codebook fp16 prep: 2 float4 per thread
    __half2* e1 = (__half2*)g_e1u;
#pragma unroll
    for (int l = 0; l < 2; l++) {
        int i4 = gid + l * 262144;
        float4 v = ((const float4*)emb)[i4];
        e1[i4 * 2 + 0] = __halves2half2(__float2half_rn(v.x), __float2half_rn(v.y));
        e1[i4 * 2 + 1] = __halves2half2(__float2half_rn(v.z), __float2half_rn(v.w));
    }
    // esq (one warp per code)
    const float* row = emb + (size_t)warp * DIM;
    float s = 0.f;
#pragma unroll
    for (int q = 0; q < 8; q++) { float v = row[lane + q * 32]; s = fmaf(v, v, s); }
#pragma unroll
    for (int o = 16; o; o >>= 1) s += __shfl_xor_sync(0xFFFFFFFFu, s, o);
    if (lane == 0) g_esq[warp] = s;
}

// ===========================================================================
// z prep: (b, d, t) fp32 -> (token, dim) fp16, transposed in smem.
// ===========================================================================
__global__ void k_prep_z(const float* __restrict__ z) {
    __shared__ float s[64][65];
    int blk = blockIdx.x;
    int tg = blk & 31, dg = (blk >> 5) & 3, b = blk >> 7;
    int tid = threadIdx.x;
    const float* zb = z + (size_t)b * DIM * TLEN;
#pragma unroll
    for (int l = 0; l < 16; l++) {
        int idx = tid + l * 256;           // 0..4095
        int d = idx >> 6, t = idx & 63;
        s[d][t] = zb[(size_t)(dg * 64 + d) * TLEN + tg * 64 + t];
    }
    __syncthreads();
    __half* z1 = (__half*)g_z1u;
#pragma unroll
    for (int l = 0; l < 16; l++) {
        int idx = tid + l * 256;
        int t = idx >> 6, d = idx & 63;
        size_t off = (size_t)(b * 2048 + tg * 64 + t) * DIM + dg * 64 + d;
        z1[off] = __float2half_rn(s[d][t]);
    }
}

// ===========================================================================
// fp16 mma.sync screen GEMM + top-2(value) + margin gate. 256 threads.
// R8 structure (best measured): CTA 256 tokens x 8192 codes, A (128KB)
// resident, chunk = 128 codes x 64 dims (16KB), 3-stage ring, wait_group 1,
// one __syncthreads per iteration, smem esq. Value-only V2 + fix-list gate.
// 8 warps 4m x 2n; warp tile 64x64. 1 CTA/SM, grid 128 -> single wave.
// ===========================================================================
#define A_OFF   0u          // 131072 = 256 rows x 512B
#define B_OFF   131072u     // 3 stages x 16384 = 49152
#define ESQ_OFF 180224u     // 32768
#define SMEM_MMA (ESQ_OFF + 32768u)   // 212992

__device__ __forceinline__ void prefetchB(uint32_t bstage, int ci, int tid) {
    const int tile = ci >> 2, c = ci & 3;
    const __half* e1 = (const __half*)g_e1u;
#pragma unroll
    for (int l = 0; l < 4; l++) {
        int idx = tid + l * 256;           // 0..1023 16B segs
        int row = idx >> 3;                // code row 0..127
        int seg = idx & 7;
        const __half* src = e1 + (size_t)(tile * 128 + row) * DIM + c * 64 + seg * 8;
        uint32_t dst = bstage + row * 128 + ((seg ^ (row & 7)) * 16);
        CP_ASYNC16(dst, (const void*)src);
    }
    CP_COMMIT();
}

// top-2 update, index for winner only (V2 needed only for margin test)
__device__ __forceinline__ void t2v(float& v1, int& i1, float& v2, float d, int code) {
    if (d < v2) {
        if (d < v1) { v2 = v1; v1 = d; i1 = code; }
        else        { v2 = d; }
    }
}

__global__ void __launch_bounds__(256, 1)
k_argmin_mma(float* __restrict__ out_idx) {
    extern __shared__ __align__(128) char smem[];
    const uint32_t sb = smem_to_u32(smem);
    const int tid = threadIdx.x, lane = tid & 31, wid = tid >> 5;
    const int wm = wid & 3, wn = wid >> 2;
    const int tok0 = blockIdx.x * 256;

    // A tile (fp16 z, 256 tokens x 256 dims) -> smem, swizzled. One group.
    {
        const __half* z1 = (const __half*)g_z1u;
#pragma unroll
        for (int l = 0; l < 32; l++) {
            int idx = tid + l * 256;       // 0..8191 16B segs
            int row = idx >> 5;            // token row 0..255
            int seg = idx & 31;
            const __half* src = z1 + (size_t)(tok0 + row) * DIM + seg * 8;
            uint32_t dst = sb + A_OFF + row * 512 + ((seg ^ (row & 7)) * 16);
            CP_ASYNC16(dst, (const void*)src);
        }
        CP_COMMIT();
    }
    prefetchB(sb + B_OFF + 0 * 16384, 0, tid);
    prefetchB(sb + B_OFF + 1 * 16384, 1, tid);

    float* esq_s = (float*)(smem + ESQ_OFF);
    for (int i = tid; i < K_CODES; i += 256) esq_s[i] = g_esq[i];

    float acc[4][8][4];
#pragma unroll
    for (int f = 0; f < 4; f++)
#pragma unroll
        for (int g = 0; g < 8; g++)
#pragma unroll
            for (int q = 0; q < 4; q++) acc[f][g][q] = 0.f;

    float v1[8], v2[8];
    int   i1[8];
#pragma unroll
    for (int r = 0; r < 8; r++) { v1[r] = CUDART_INF_F; v2[r] = CUDART_INF_F; i1[r] = 0; }

    for (int ci = 0; ci < 256; ci++) {
        if (ci < 254) { CP_WAIT1(); } else { CP_WAIT0(); }
        __syncthreads();
        if (ci + 2 < 256)
            prefetchB(sb + B_OFF + ((ci + 2) % 3) * 16384, ci + 2, tid);

        const uint32_t bb = sb + B_OFF + (ci % 3) * 16384;
        const int c = ci & 3;
#pragma unroll
        for (int kk = 0; kk < 4; kk++) {
            uint32_t a[4][4];
            const int aseg = 8 * c + 2 * kk + (lane >> 4);
#pragma unroll
            for (int f = 0; f < 4; f++) {
                int r = 64 * wm + 16 * f + (lane & 15);
                uint32_t addr = sb + A_OFF + r * 512 + ((aseg ^ (r & 7)) * 16);
                ldsm_x4(a[f], addr);
            }
            uint32_t bfr[8][2];
            const int bseg = 2 * kk + (lane >> 4);
#pragma unroll
            for (int ng = 0; ng < 4; ng++) {
                int r = 64 * wn + 16 * ng + (lane & 15);
                uint32_t addr = bb + r * 128 + ((bseg ^ (r & 7)) * 16);
                uint32_t t4[4];
                ldsm_x4(t4, addr);
                bfr[2 * ng][0] = t4[0]; bfr[2 * ng + 1][0] = t4[1];
                bfr[2 * ng][1] = t4[2]; bfr[2 * ng + 1][1] = t4[3];
            }
#pragma unroll
            for (int f = 0; f < 4; f++)
#pragma unroll
                for (int g = 0; g < 8; g++)
                    mma_16816(acc[f][g], a[f], bfr[g]);
        }

        if (c == 3) {
            const int tile = ci >> 2;
#pragma unroll
            for (int f = 0; f < 4; f++)
#pragma unroll
                for (int g = 0; g < 8; g++) {
                    int col = tile * 128 + 64 * wn + 8 * g + (lane & 3) * 2;
                    float2 eq = *(const float2*)(esq_s + col);
                    float d0 = fmaf(-2.f, acc[f][g][0], eq.x);
                    float d1 = fmaf(-2.f, acc[f][g][1], eq.y);
                    float d2 = fmaf(-2.f, acc[f][g][2], eq.x);
                    float d3 = fmaf(-2.f, acc[f][g][3], eq.y);
                    t2v(v1[2*f], i1[2*f], v2[2*f], d0, col);
                    t2v(v1[2*f], i1[2*f], v2[2*f], d1, col + 1);
                    t2v(v1[2*f+1], i1[2*f+1], v2[2*f+1], d2, col);
                    t2v(v1[2*f+1], i1[2*f+1], v2[2*f+1], d3, col + 1);
                    acc[f][g][0] = 0.f; acc[f][g][1] = 0.f;
                    acc[f][g][2] = 0.f; acc[f][g][3] = 0.f;
                }
        }
    }

    // ---- cross-thread top-2 merge (8 contributors per token row) ----
    __syncthreads();
    float4* red = (float4*)(smem + B_OFF);    // [256][8], reuses B stages
#pragma unroll
    for (int f = 0; f < 4; f++)
#pragma unroll
        for (int h = 0; h < 2; h++) {
            int row = 64 * wm + 16 * f + 8 * h + (lane >> 2);
            int contrib = wn * 4 + (lane & 3);
            int t2 = 2 * f + h;
            red[row * 8 + contrib] = make_float4(v1[t2], __int_as_float(i1[t2]),
                                                 v2[t2], 0.f);
        }
    __syncthreads();
    {
        float V1 = CUDART_INF_F, V2 = CUDART_INF_F;
        int I1 = 0;
#pragma unroll 2
        for (int c8 = 0; c8 < 8; c8++) {
            float4 rec = red[tid * 8 + c8];
            float va = rec.x; int ia = __float_as_int(rec.y);
            float vb = rec.z;
            if (va < V1 || (va == V1 && ia < I1)) { V2 = V1; V1 = va; I1 = ia; }
            else if (va < V2) { V2 = va; }
            if (vb < V2) V2 = vb;
        }
        int token = tok0 + tid;
        g_idx[token] = I1;                 // provisional
        out_idx[token] = (float)I1;
        if (V2 - V1 < MARGIN) {
            int slot = atomicAdd(&g_nfix, 1);
            g_fixlist[slot] = token;
        }
    }
}

// ===========================================================================
// Exact fp32 rescan for contested tokens — smem-tiled, coalesced, split into
// 4 codebook quarters per group. NOW 2 CTAs/SM: chunk = 32 codes (33.3KB x2
// buffers + 36.8KB zt = 101KB smem). Thread: code c = tid&31, tokens
// 4*(tid>>5)..+3 (z loads are warp-broadcast float4s; e rows conflict-free).
// Per-(token,code) arithmetic identical to prior passing rescore:
// ascending-d fmaf chain, eq - 2*a, strict-< ascending code.
// ===========================================================================
#define R_ES0   0u
#define R_ES1   33280u            // 32 rows x 1040B
#define R_ZT    66560u            // 256 x 36 x 4B = 36864
#define SMEM_RES (R_ZT + 36864u)  // 103424

__device__ __forceinline__ void r_prefetch(uint32_t dst, const float* __restrict__ emb,
                                           int ch, int tid) {
#pragma unroll
    for (int l = 0; l < 8; l++) {
        int idx = tid + l * 256;          // 0..2047 16B segs
        int row = idx >> 6;               // code row 0..31
        int seg = idx & 63;               // 16B seg within 1KB row
        const float* src = emb + (size_t)(ch * 32 + row) * DIM + seg * 4;
        CP_ASYNC16(dst + row * 1040 + seg * 16, (const void*)src);
    }
    CP_COMMIT();
}

__global__ void __launch_bounds__(256, 2)
k_rescore(const float* __restrict__ z, const float* __restrict__ emb) {
    extern __shared__ __align__(128) char smem[];
    const uint32_t sb = smem_to_u32(smem);
    float* zt = (float*)(smem + R_ZT);
    const int tid = threadIdx.x;
    const int c = tid & 31, g = tid >> 5;   // code-in-chunk, token group (4 tokens)
    const int nfix = g_nfix;
    const int npairs = ((nfix + 31) >> 5) * 4;

    for (int p = blockIdx.x; p < npairs; p += gridDim.x) {
        const int grp = p >> 2, q = p & 3;
        __syncthreads();                  // smem reuse from previous pair
        // stage 32 token z-columns: zt[d][tok], thread = d
        {
            int base = grp * 32;
#pragma unroll 4
            for (int i = 0; i < 32; i++) {
                int slot = base + i; if (slot >= nfix) slot = nfix - 1;
                int token = g_fixlist[slot];
                int b = token >> 11, tt = token & 2047;
                zt[tid * 36 + i] = z[(size_t)b * DIM * TLEN + (size_t)tid * TLEN + tt];
            }
        }
        r_prefetch(sb + R_ES0, emb, q * 64, tid);   // chunk index base = q*64
        __syncthreads();                  // zt visible

        float bv[4]; int bi[4];
#pragma unroll
        for (int i = 0; i < 4; i++) { bv[i] = CUDART_INF_F; bi[i] = 0; }

        for (int cc = 0; cc < 64; cc++) {
            const int ch = q * 64 + cc;   // global 32-code chunk index
            __syncthreads();              // all done reading the other buffer
            if (cc + 1 < 64) {
                r_prefetch(sb + (((cc + 1) & 1) ? R_ES1 : R_ES0), emb, ch + 1, tid);
                CP_WAIT1();
            } else {
                CP_WAIT0();
            }
            __syncthreads();              // chunk visible

            const float* esb = (const float*)(smem + ((cc & 1) ? R_ES1 : R_ES0));
            float a0 = 0.f, a1 = 0.f, a2 = 0.f, a3 = 0.f;
#pragma unroll 8
            for (int d = 0; d < 256; d += 4) {
                float4 e4 = *(const float4*)(esb + c * 260 + d);
                float4 z0 = *(const float4*)(zt + (d + 0) * 36 + 4 * g);
                float4 zA = *(const float4*)(zt + (d + 1) * 36 + 4 * g);
                float4 zB = *(const float4*)(zt + (d + 2) * 36 + 4 * g);
                float4 zC = *(const float4*)(zt + (d + 3) * 36 + 4 * g);
                a0 = fmaf(z0.x, e4.x, a0); a1 = fmaf(z0.y, e4.x, a1);
                a2 = fmaf(z0.z, e4.x, a2); a3 = fmaf(z0.w, e4.x, a3);
                a0 = fmaf(zA.x, e4.y, a0); a1 = fmaf(zA.y, e4.y, a1);
                a2 = fmaf(zA.z, e4.y, a2); a3 = fmaf(zA.w, e4.y, a3);
                a0 = fmaf(zB.x, e4.z, a0); a1 = fmaf(zB.y, e4.z, a1);
                a2 = fmaf(zB.z, e4.z, a2); a3 = fmaf(zB.w, e4.z, a3);
                a0 = fmaf(zC.x, e4.w, a0); a1 = fmaf(zC.y, e4.w, a1);
                a2 = fmaf(zC.z, e4.w, a2); a3 = fmaf(zC.w, e4.w, a3);
            }
            int code = ch * 32 + c;
            float eq = __ldg(g_esq + code);
            float d0 = eq - 2.0f * a0;
            float d1 = eq - 2.0f * a1;
            float d2 = eq - 2.0f * a2;
            float d3 = eq - 2.0f * a3;
            if (d0 < bv[0]) { bv[0] = d0; bi[0] = code; }  // ascending: first min
            if (d1 < bv[1]) { bv[1] = d1; bi[1] = code; }
            if (d2 < bv[2]) { bv[2] = d2; bi[2] = code; }
            if (d3 < bv[3]) { bv[3] = d3; bi[3] = code; }
        }

        // ---- reduction: 32 candidates per token -> quarter partial ----
        __syncthreads();
        float* rv = (float*)smem;             // [32][32] floats, reuses es0
        int*   ri = (int*)(smem + 4096);      // [32][32] ints
#pragma unroll
        for (int i = 0; i < 4; i++) {
            int tok = 4 * g + i;
            rv[tok * 32 + c] = bv[i];
            ri[tok * 32 + c] = bi[i];
        }
        __syncthreads();
        if (tid < 32 && grp * 32 + tid < nfix) {
            float V = CUDART_INF_F; int I = 0;
            for (int j = 0; j < 32; j++) {
                float v = rv[tid * 32 + j]; int id = ri[tid * 32 + j];
                if (v < V || (v == V && id < I)) { V = v; I = id; }
            }
            int slot = grp * 32 + tid;
            g_pv[slot * 4 + q] = V;
            g_pi[slot * 4 + q] = I;
        }
    }
}

// Fold the 4 quarter partials per contested token (ascending q = ascending
// code ranges; strict < keeps the earliest = lowest code -> first-min).
__global__ void k_fixmerge(float* __restrict__ out_idx) {
    int s = blockIdx.x * blockDim.x + threadIdx.x;
    if (s >= g_nfix) return;
    float V = g_pv[s * 4]; int I = g_pi[s * 4];
#pragma unroll
    for (int q = 1; q < 4; q++) {
        float v = g_pv[s * 4 + q];
        if (v < V) { V = v; I = g_pi[s * 4 + q]; }
    }
    int token = g_fixlist[s];
    g_idx[token] = I;
    out_idx[token] = (float)I;
}

// ===========================================================================
// Fused counts/sum_embeddings scatter, z_q gather, commitment-loss partial.
// grid (NTOK/256, 4). e-rows for this 64-dim chunk staged in smem via
// coalesced cooperative loads.
// ===========================================================================
#define SMEM_SG (1024u + 256u * 65u * 4u)   // sidx + es[256][65]

__global__ void k_scatter_gather(const float* __restrict__ z,
                                 const float* __restrict__ emb,
                                 float* __restrict__ out_zq) {
    extern __shared__ __align__(16) char smg[];
    int* sidx = (int*)smg;
    float* es = (float*)(smg + 1024);

    int tid   = threadIdx.x;
    int lane  = tid & 31;
    int w     = tid >> 5;
    int tok0  = blockIdx.x * 256;
    int b     = tok0 >> 11;
    int tl    = (tok0 & 2047) + tid;
    int token = tok0 + tid;
    int idx   = g_idx[token];
    sidx[tid] = idx;
    if (blockIdx.y == 0) atomicAdd(&g_counts[idx], 1.0f);
    __syncthreads();

    int d0 = blockIdx.y * 64;
#pragma unroll
    for (int j = 0; j < 16; j++) {
        int ta  = w * 32 + 2 * j + (lane >> 4);
        int seg = lane & 15;
        float4 v = *(const float4*)(emb + (size_t)sidx[ta] * DIM + d0 + seg * 4);
        float* dst = es + ta * 65 + seg * 4;
        dst[0] = v.x; dst[1] = v.y; dst[2] = v.z; dst[3] = v.w;
    }
    __syncthreads();

    const float* zb = z + (size_t)b * DIM * TLEN;
    float*       ob = out_zq + (size_t)b * DIM * TLEN;
    float* sr = g_sumemb + (size_t)idx * DIM;
    const float* myrow = es + tid * 65;

    float lacc = 0.f;
#pragma unroll 8
    for (int dd = 0; dd < 64; dd++) {
        int d = d0 + dd;
        float zv = zb[(size_t)d * TLEN + tl];
        float ev = myrow[dd];
        ob[(size_t)d * TLEN + tl] = zv + (ev - zv);   // straight-through
        atomicAdd(sr + d, zv);
        float df = zv - ev;
        lacc = fmaf(df, df, lacc);
    }
#pragma unroll
    for (int o = 16; o; o >>= 1) lacc += __shfl_xor_sync(0xFFFFFFFFu, lacc, o);
    if (lane == 0) atomicAdd(&g_scal[0], lacc);
}

// ===========================================================================
// Single block: new_cluster_size, n, utilization, loss.
// ===========================================================================
__global__ void k_reduce(const float* __restrict__ cs,
                         float* __restrict__ out_ncs,
                         float* __restrict__ out_loss,
                         float* __restrict__ out_util) {
    __shared__ float sn[256];
    __shared__ float sz[256];
    int tid = threadIdx.x;
    const float om = (float)(1.0 - 0.99);
    float nsum = 0.f, nz = 0.f;
    for (int k = tid; k < K_CODES; k += 256) {
        float c   = g_counts[k];
        float ncs = cs[k] * 0.99f + om * c;
        out_ncs[k] = ncs;
        nsum += ncs;
        nz += (c > 0.f) ? 1.f : 0.f;
    }
    sn[tid] = nsum; sz[tid] = nz;
    __syncthreads();
    for (int s = 128; s; s >>= 1) {
        if (tid < s) { sn[tid] += sn[tid + s]; sz[tid] += sz[tid + s]; }
        __syncthreads();
    }
    if (tid == 0) {
        g_scal[1] = sn[0];
        *out_loss = 1.0f * (g_scal[0] / (float)(NTOK * DIM));
        *out_util = sz[0] / (float)K_CODES;
    }
}

// ===========================================================================
// Elementwise EMA update.
// ===========================================================================
__global__ void k_update(const float* __restrict__ cs,
                         const float* __restrict__ ea,
                         float* __restrict__ out_nemb,
                         float* __restrict__ out_nea) {
    int gid = blockIdx.x * blockDim.x + threadIdx.x;
    int k = gid >> 8;
    const float om = (float)(1.0 - 0.99);
    float n   = g_scal[1];
    float ncs = cs[k] * 0.99f + om * g_counts[k];
    float smoothed = (ncs + 1e-5f) / (n + (float)(K_CODES * 1e-5)) * n;
    float nav = ea[gid] * 0.99f + om * g_sumemb[gid];
    out_nea[gid]  = nav;
    out_nemb[gid] = nav / smoothed;
}

// ===========================================================================
extern "C" void kernel_launch(void* const* d_in, const int* in_sizes, int n_in,
                              void* d_out, int out_size) {
    const float* z   = (const float*)d_in[0];   // (16, 256, 2048)
    const float* emb = (const float*)d_in[1];   // (8192, 256)
    const float* cs  = (const float*)d_in[2];   // (8192,)
    const float* ea  = (const float*)d_in[3];   // (8192, 256)
    float* out = (float*)d_out;

    float* o_zq   = out + OFF_ZQ;
    float* o_idx  = out + OFF_IDX;
    float* o_loss = out + OFF_LOSS;
    float* o_nemb = out + OFF_NEMB;
    float* o_ncs  = out + OFF_NCS;
    float* o_nea  = out + OFF_NEA;
    float* o_util = out + OFF_UTIL;

    cudaFuncSetAttribute(k_argmin_mma,
                         cudaFuncAttributeMaxDynamicSharedMemorySize, SMEM_MMA);
    cudaFuncSetAttribute(k_rescore,
                         cudaFuncAttributeMaxDynamicSharedMemorySize, SMEM_RES);
    cudaFuncSetAttribute(k_scatter_gather,
                         cudaFuncAttributeMaxDynamicSharedMemorySize, SMEM_SG);

    k_init_esq_prep<<<1024, 256>>>(emb);                  // launch 1
    k_prep_z<<<2048, 256>>>(z);                           // launch 2
    k_argmin_mma<<<NTOK / 256, 256, SMEM_MMA>>>(o_idx);   // launch 3
    k_rescore<<<512, 256, SMEM_RES>>>(z, emb);            // launch 4
    k_fixmerge<<<NTOK / 256, 256>>>(o_idx);               // launch 5
    dim3 sg_grid(NTOK / 256, 4);
    k_scatter_gather<<<sg_grid, 256, SMEM_SG>>>(z, emb, o_zq);  // launch 6
    k_reduce<<<1, 256>>>(cs, o_ncs, o_loss, o_util);      // launch 7
    k_update<<<K_CODES * DIM / 256, 256>>>(cs, ea, o_nemb, o_nea);  // launch 8
}

// round 16
// speedup vs baseline: 1.1339x; 1.1339x over previous
#include <cuda_runtime.h>
#include <cuda_fp16.h>
#include <math_constants.h>
#include <cstdint>

// Problem constants
#define K_CODES 8192
#define DIM     256
#define TLEN    2048
#define BATCH   16
#define NTOK    32768           // BATCH*TLEN

// Output layout (float32, concatenated in reference-return order)
#define OFF_ZQ    0ull
#define OFF_IDX   8388608ull
#define OFF_LOSS  8421376ull
#define OFF_NEMB  8421377ull
#define OFF_NCS   10518529ull
#define OFF_NEA   10526721ull
#define OFF_UTIL  12623873ull

#define MARGIN 0.15f
#define NSLICE 16               // rescore codebook slices per group

// Scratch (device globals; no allocation allowed). uint4 for 16B alignment.
__device__ float g_esq[K_CODES];
__device__ int   g_idx[NTOK];
__device__ float g_counts[K_CODES];
__device__ float g_sumemb[K_CODES * DIM];
__device__ float g_scal[4];   // [0]=loss partial sum, [1]=n
__device__ int   g_nfix;
__device__ int   g_fixlist[NTOK];
__device__ float g_pv[NTOK * NSLICE];       // rescore partial min value per slice
__device__ int   g_pi[NTOK * NSLICE];       // rescore partial min index per slice
__device__ uint4 g_z1u[NTOK * DIM / 8];     // fp16 z, (token, dim)
__device__ uint4 g_e1u[K_CODES * DIM / 8];  // fp16 codebook, (code, dim)
__device__ float g_zt32[NTOK * DIM];        // fp32 z, (token, dim) transposed copy

// ===========================================================================
// PTX helpers (plain sm_80+ features — tcgen05 unavailable on compute_100)
// ===========================================================================
__device__ __forceinline__ uint32_t smem_to_u32(const void* smem_ptr) {
    uint32_t addr;
    asm("{ .reg .u64 tmp; cvta.to.shared.u64 tmp, %1; cvt.u32.u64 %0, tmp; }"
        : "=r"(addr) : "l"(smem_ptr));
    return addr;
}

#define CP_ASYNC16(dst, src) \
    asm volatile("cp.async.cg.shared.global [%0], [%1], 16;" :: "r"(dst), "l"(src) : "memory")
#define CP_COMMIT() asm volatile("cp.async.commit_group;" ::: "memory")
#define CP_WAIT1()  asm volatile("cp.async.wait_group 1;" ::: "memory")
#define CP_WAIT0()  asm volatile("cp.async.wait_group 0;" ::: "memory")

__device__ __forceinline__ void ldsm_x4(uint32_t* r, uint32_t addr) {
    asm volatile("ldmatrix.sync.aligned.m8n8.x4.shared.b16 {%0,%1,%2,%3}, [%4];"
        : "=r"(r[0]), "=r"(r[1]), "=r"(r[2]), "=r"(r[3]) : "r"(addr));
}

__device__ __forceinline__ void mma_16816(float* c, const uint32_t* a, const uint32_t* b) {
    asm volatile(
        "mma.sync.aligned.m16n8k16.row.col.f32.f16.f16.f32 "
        "{%0,%1,%2,%3}, {%4,%5,%6,%7}, {%8,%9}, {%0,%1,%2,%3};"
        : "+f"(c[0]), "+f"(c[1]), "+f"(c[2]), "+f"(c[3])
        : "r"(a[0]), "r"(a[1]), "r"(a[2]), "r"(a[3]), "r"(b[0]), "r"(b[1]));
}

// ===========================================================================
// Fused zero-scratch + esq + codebook fp16 prep. grid 1024 x 256.
// ===========================================================================
__global__ void k_init_esq_prep(const float* __restrict__ emb) {
    int gid  = blockIdx.x * blockDim.x + threadIdx.x;   // 0..262143
    int warp = gid >> 5;                                // 0..8191
    int lane = threadIdx.x & 31;
    ((float4*)g_sumemb)[gid] = make_float4(0.f, 0.f, 0.f, 0.f);
    ((float4*)g_sumemb)[gid + 262144] = make_float4(0.f, 0.f, 0.f, 0.f);
    if (gid < K_CODES) g_counts[gid] = 0.f;
    if (gid < 4) g_scal[gid] = 0.f;
    if (gid == 0) g_nfix = 0;
    // codebook fp16 prep: 2 float4 per thread
    __half2* e1 = (__half2*)g_e1u;
#pragma unroll
    for (int l = 0; l < 2; l++) {
        int i4 = gid + l * 262144;
        float4 v = ((const float4*)emb)[i4];
        e1[i4 * 2 + 0] = __halves2half2(__float2half_rn(v.x), __float2half_rn(v.y));
        e1[i4 * 2 + 1] = __halves2half2(__float2half_rn(v.z), __float2half_rn(v.w));
    }
    // esq (one warp per code)
    const float* row = emb + (size_t)warp * DIM;
    float s = 0.f;
#pragma unroll
    for (int q = 0; q < 8; q++) { float v = row[lane + q * 32]; s = fmaf(v, v, s); }
#pragma unroll
    for (int o = 16; o; o >>= 1) s += __shfl_xor_sync(0xFFFFFFFFu, s, o);
    if (lane == 0) g_esq[warp] = s;
}

// ===========================================================================
// z prep: (b, d, t) fp32 -> (token, dim) fp16 AND fp32 transposed copies.
// ===========================================================================
__global__ void k_prep_z(const float* __restrict__ z) {
    __shared__ float s[64][65];
    int blk = blockIdx.x;
    int tg = blk & 31, dg = (blk >> 5) & 3, b = blk >> 7;
    int tid = threadIdx.x;
    const float* zb = z + (size_t)b * DIM * TLEN;
#pragma unroll
    for (int l = 0; l < 16; l++) {
        int idx = tid + l * 256;           // 0..4095
        int d = idx >> 6, t = idx & 63;
        s[d][t] = zb[(size_t)(dg * 64 + d) * TLEN + tg * 64 + t];
    }
    __syncthreads();
    __half* z1 = (__half*)g_z1u;
#pragma unroll
    for (int l = 0; l < 16; l++) {
        int idx = tid + l * 256;
        int t = idx >> 6, d = idx & 63;
        float v = s[d][t];
        size_t off = (size_t)(b * 2048 + tg * 64 + t) * DIM + dg * 64 + d;
        z1[off] = __float2half_rn(v);
        g_zt32[off] = v;
    }
}

// ===========================================================================
// fp16 mma.sync screen GEMM + top-2(value) + margin gate. 256 threads.
// R8 structure (best measured): CTA 256 tokens x 8192 codes, A (128KB)
// resident, chunk = 128 codes x 64 dims (16KB), 3-stage ring, wait_group 1,
// one __syncthreads per iteration, smem esq. Value-only V2 + fix-list gate.
// 8 warps 4m x 2n; warp tile 64x64. 1 CTA/SM, grid 128 -> single wave.
// ===========================================================================
#define A_OFF   0u          // 131072 = 256 rows x 512B
#define B_OFF   131072u     // 3 stages x 16384 = 49152
#define ESQ_OFF 180224u     // 32768
#define SMEM_MMA (ESQ_OFF + 32768u)   // 212992

__device__ __forceinline__ void prefetchB(uint32_t bstage, int ci, int tid) {
    const int tile = ci >> 2, c = ci & 3;
    const __half* e1 = (const __half*)g_e1u;
#pragma unroll
    for (int l = 0; l < 4; l++) {
        int idx = tid + l * 256;           // 0..1023 16B segs
        int row = idx >> 3;                // code row 0..127
        int seg = idx & 7;
        const __half* src = e1 + (size_t)(tile * 128 + row) * DIM + c * 64 + seg * 8;
        uint32_t dst = bstage + row * 128 + ((seg ^ (row & 7)) * 16);
        CP_ASYNC16(dst, (const void*)src);
    }
    CP_COMMIT();
}

// top-2 update, index for winner only (V2 needed only for margin test)
__device__ __forceinline__ void t2v(float& v1, int& i1, float& v2, float d, int code) {
    if (d < v2) {
        if (d < v1) { v2 = v1; v1 = d; i1 = code; }
        else        { v2 = d; }
    }
}

__global__ void __launch_bounds__(256, 1)
k_argmin_mma(float* __restrict__ out_idx) {
    extern __shared__ __align__(128) char smem[];
    const uint32_t sb = smem_to_u32(smem);
    const int tid = threadIdx.x, lane = tid & 31, wid = tid >> 5;
    const int wm = wid & 3, wn = wid >> 2;
    const int tok0 = blockIdx.x * 256;

    // A tile (fp16 z, 256 tokens x 256 dims) -> smem, swizzled. One group.
    {
        const __half* z1 = (const __half*)g_z1u;
#pragma unroll
        for (int l = 0; l < 32; l++) {
            int idx = tid + l * 256;       // 0..8191 16B segs
            int row = idx >> 5;            // token row 0..255
            int seg = idx & 31;
            const __half* src = z1 + (size_t)(tok0 + row) * DIM + seg * 8;
            uint32_t dst = sb + A_OFF + row * 512 + ((seg ^ (row & 7)) * 16);
            CP_ASYNC16(dst, (const void*)src);
        }
        CP_COMMIT();
    }
    prefetchB(sb + B_OFF + 0 * 16384, 0, tid);
    prefetchB(sb + B_OFF + 1 * 16384, 1, tid);

    float* esq_s = (float*)(smem + ESQ_OFF);
    for (int i = tid; i < K_CODES; i += 256) esq_s[i] = g_esq[i];

    float acc[4][8][4];
#pragma unroll
    for (int f = 0; f < 4; f++)
#pragma unroll
        for (int g = 0; g < 8; g++)
#pragma unroll
            for (int q = 0; q < 4; q++) acc[f][g][q] = 0.f;

    float v1[8], v2[8];
    int   i1[8];
#pragma unroll
    for (int r = 0; r < 8; r++) { v1[r] = CUDART_INF_F; v2[r] = CUDART_INF_F; i1[r] = 0; }

    for (int ci = 0; ci < 256; ci++) {
        if (ci < 254) { CP_WAIT1(); } else { CP_WAIT0(); }
        __syncthreads();
        if (ci + 2 < 256)
            prefetchB(sb + B_OFF + ((ci + 2) % 3) * 16384, ci + 2, tid);

        const uint32_t bb = sb + B_OFF + (ci % 3) * 16384;
        const int c = ci & 3;
#pragma unroll
        for (int kk = 0; kk < 4; kk++) {
            uint32_t a[4][4];
            const int aseg = 8 * c + 2 * kk + (lane >> 4);
#pragma unroll
            for (int f = 0; f < 4; f++) {
                int r = 64 * wm + 16 * f + (lane & 15);
                uint32_t addr = sb + A_OFF + r * 512 + ((aseg ^ (r & 7)) * 16);
                ldsm_x4(a[f], addr);
            }
            uint32_t bfr[8][2];
            const int bseg = 2 * kk + (lane >> 4);
#pragma unroll
            for (int ng = 0; ng < 4; ng++) {
                int r = 64 * wn + 16 * ng + (lane & 15);
                uint32_t addr = bb + r * 128 + ((bseg ^ (r & 7)) * 16);
                uint32_t t4[4];
                ldsm_x4(t4, addr);
                bfr[2 * ng][0] = t4[0]; bfr[2 * ng + 1][0] = t4[1];
                bfr[2 * ng][1] = t4[2]; bfr[2 * ng + 1][1] = t4[3];
            }
#pragma unroll
            for (int f = 0; f < 4; f++)
#pragma unroll
                for (int g = 0; g < 8; g++)
                    mma_16816(acc[f][g], a[f], bfr[g]);
        }

        if (c == 3) {
            const int tile = ci >> 2;
#pragma unroll
            for (int f = 0; f < 4; f++)
#pragma unroll
                for (int g = 0; g < 8; g++) {
                    int col = tile * 128 + 64 * wn + 8 * g + (lane & 3) * 2;
                    float2 eq = *(const float2*)(esq_s + col);
                    float d0 = fmaf(-2.f, acc[f][g][0], eq.x);
                    float d1 = fmaf(-2.f, acc[f][g][1], eq.y);
                    float d2 = fmaf(-2.f, acc[f][g][2], eq.x);
                    float d3 = fmaf(-2.f, acc[f][g][3], eq.y);
                    t2v(v1[2*f], i1[2*f], v2[2*f], d0, col);
                    t2v(v1[2*f], i1[2*f], v2[2*f], d1, col + 1);
                    t2v(v1[2*f+1], i1[2*f+1], v2[2*f+1], d2, col);
                    t2v(v1[2*f+1], i1[2*f+1], v2[2*f+1], d3, col + 1);
                    acc[f][g][0] = 0.f; acc[f][g][1] = 0.f;
                    acc[f][g][2] = 0.f; acc[f][g][3] = 0.f;
                }
        }
    }

    // ---- cross-thread top-2 merge (8 contributors per token row) ----
    __syncthreads();
    float4* red = (float4*)(smem + B_OFF);    // [256][8], reuses B stages
#pragma unroll
    for (int f = 0; f < 4; f++)
#pragma unroll
        for (int h = 0; h < 2; h++) {
            int row = 64 * wm + 16 * f + 8 * h + (lane >> 2);
            int contrib = wn * 4 + (lane & 3);
            int t2 = 2 * f + h;
            red[row * 8 + contrib] = make_float4(v1[t2], __int_as_float(i1[t2]),
                                                 v2[t2], 0.f);
        }
    __syncthreads();
    {
        float V1 = CUDART_INF_F, V2 = CUDART_INF_F;
        int I1 = 0;
#pragma unroll 2
        for (int c8 = 0; c8 < 8; c8++) {
            float4 rec = red[tid * 8 + c8];
            float va = rec.x; int ia = __float_as_int(rec.y);
            float vb = rec.z;
            if (va < V1 || (va == V1 && ia < I1)) { V2 = V1; V1 = va; I1 = ia; }
            else if (va < V2) { V2 = va; }
            if (vb < V2) V2 = vb;
        }
        int token = tok0 + tid;
        g_idx[token] = I1;                 // provisional
        out_idx[token] = (float)I1;
        if (V2 - V1 < MARGIN) {
            int slot = atomicAdd(&g_nfix, 1);
            g_fixlist[slot] = token;
        }
    }
}

// ===========================================================================
// Exact fp32 rescan for contested tokens. Block = (group of 32 tokens,
// codebook slice of 512 codes) — 16 slices per group so per-pair serial work
// is 1/4 of the old quarter scheme (latency-bound fix). zt staged COALESCED
// from g_zt32 (fp32 (token,dim) copy). Codebook streamed in 64-code chunks,
// double-buffered. Per-(token,code) arithmetic identical to prior passing
// rescore: ascending-d fmaf chain, eq - 2*a, strict-< ascending code.
// Partials g_pv/g_pi[slot*16+sl]; k_fixmerge folds slices ascending.
// ===========================================================================
#define R_ES0   0u
#define R_ES1   66560u            // 64 rows x 1040B
#define R_ZT    133120u           // 256 x 36 x 4B = 36864
#define SMEM_RES (R_ZT + 36864u)  // 169984

__device__ __forceinline__ void r_prefetch(uint32_t dst, const float* __restrict__ emb,
                                           int ch, int tid) {
#pragma unroll
    for (int l = 0; l < 16; l++) {
        int idx = tid + l * 256;          // 0..4095 16B segs
        int row = idx >> 6;               // code row 0..63
        int seg = idx & 63;               // 16B seg within 1KB row
        const float* src = emb + (size_t)(ch * 64 + row) * DIM + seg * 4;
        CP_ASYNC16(dst + row * 1040 + seg * 16, (const void*)src);
    }
    CP_COMMIT();
}

__global__ void __launch_bounds__(256, 1)
k_rescore(const float* __restrict__ emb) {
    extern __shared__ __align__(128) char smem[];
    const uint32_t sb = smem_to_u32(smem);
    float* zt = (float*)(smem + R_ZT);
    const int tid = threadIdx.x;
    const int c = tid & 63, h = tid >> 6;
    const int nfix = g_nfix;
    const int npairs = ((nfix + 31) >> 5) * NSLICE;

    for (int p = blockIdx.x; p < npairs; p += gridDim.x) {
        const int grp = p >> 4, sl = p & (NSLICE - 1);
        __syncthreads();                  // smem reuse from previous pair
        // stage 32 token z-rows COALESCED from g_zt32 -> zt[d][tok]
        {
            int base = grp * 32;
#pragma unroll
            for (int l = 0; l < 8; l++) {
                int idx = tid + l * 256;      // 0..2047 float4 units
                int tok = idx >> 6;           // 0..31
                int seg = idx & 63;           // float4 seg (4 dims)
                int slot = base + tok; if (slot >= nfix) slot = nfix - 1;
                int token = g_fixlist[slot];
                float4 v = *(const float4*)(g_zt32 + (size_t)token * DIM + seg * 4);
                zt[(seg * 4 + 0) * 36 + tok] = v.x;
                zt[(seg * 4 + 1) * 36 + tok] = v.y;
                zt[(seg * 4 + 2) * 36 + tok] = v.z;
                zt[(seg * 4 + 3) * 36 + tok] = v.w;
            }
        }
        r_prefetch(sb + R_ES0, emb, sl * 8, tid);   // 64-code chunks; 8 per slice
        __syncthreads();                  // zt visible

        float bv[8]; int bi[8];
#pragma unroll
        for (int i = 0; i < 8; i++) { bv[i] = CUDART_INF_F; bi[i] = 0; }

        for (int cc = 0; cc < 8; cc++) {
            const int ch = sl * 8 + cc;
            __syncthreads();              // all done reading the other buffer
            if (cc + 1 < 8) {
                r_prefetch(sb + (((cc + 1) & 1) ? R_ES1 : R_ES0), emb, ch + 1, tid);
                CP_WAIT1();
            } else {
                CP_WAIT0();
            }
            __syncthreads();              // chunk visible

            const float* esb = (const float*)(smem + ((cc & 1) ? R_ES1 : R_ES0));
            float a[8];
#pragma unroll
            for (int i = 0; i < 8; i++) a[i] = 0.f;
#pragma unroll 4
            for (int d = 0; d < 256; d += 4) {
                float4 e4 = *(const float4*)(esb + c * 260 + d);
                float4 z0a = *(const float4*)(zt + (d + 0) * 36 + 8 * h);
                float4 z0b = *(const float4*)(zt + (d + 0) * 36 + 8 * h + 4);
                float4 z1a = *(const float4*)(zt + (d + 1) * 36 + 8 * h);
                float4 z1b = *(const float4*)(zt + (d + 1) * 36 + 8 * h + 4);
                float4 z2a = *(const float4*)(zt + (d + 2) * 36 + 8 * h);
                float4 z2b = *(const float4*)(zt + (d + 2) * 36 + 8 * h + 4);
                float4 z3a = *(const float4*)(zt + (d + 3) * 36 + 8 * h);
                float4 z3b = *(const float4*)(zt + (d + 3) * 36 + 8 * h + 4);
                a[0] = fmaf(z0a.x, e4.x, a[0]); a[1] = fmaf(z0a.y, e4.x, a[1]);
                a[2] = fmaf(z0a.z, e4.x, a[2]); a[3] = fmaf(z0a.w, e4.x, a[3]);
                a[4] = fmaf(z0b.x, e4.x, a[4]); a[5] = fmaf(z0b.y, e4.x, a[5]);
                a[6] = fmaf(z0b.z, e4.x, a[6]); a[7] = fmaf(z0b.w, e4.x, a[7]);
                a[0] = fmaf(z1a.x, e4.y, a[0]); a[1] = fmaf(z1a.y, e4.y, a[1]);
                a[2] = fmaf(z1a.z, e4.y, a[2]); a[3] = fmaf(z1a.w, e4.y, a[3]);
                a[4] = fmaf(z1b.x, e4.y, a[4]); a[5] = fmaf(z1b.y, e4.y, a[5]);
                a[6] = fmaf(z1b.z, e4.y, a[6]); a[7] = fmaf(z1b.w, e4.y, a[7]);
                a[0] = fmaf(z2a.x, e4.z, a[0]); a[1] = fmaf(z2a.y, e4.z, a[1]);
                a[2] = fmaf(z2a.z, e4.z, a[2]); a[3] = fmaf(z2a.w, e4.z, a[3]);
                a[4] = fmaf(z2b.x, e4.z, a[4]); a[5] = fmaf(z2b.y, e4.z, a[5]);
                a[6] = fmaf(z2b.z, e4.z, a[6]); a[7] = fmaf(z2b.w, e4.z, a[7]);
                a[0] = fmaf(z3a.x, e4.w, a[0]); a[1] = fmaf(z3a.y, e4.w, a[1]);
                a[2] = fmaf(z3a.z, e4.w, a[2]); a[3] = fmaf(z3a.w, e4.w, a[3]);
                a[4] = fmaf(z3b.x, e4.w, a[4]); a[5] = fmaf(z3b.y, e4.w, a[5]);
                a[6] = fmaf(z3b.z, e4.w, a[6]); a[7] = fmaf(z3b.w, e4.w, a[7]);
            }
            int code = ch * 64 + c;
            float eq = __ldg(g_esq + code);
#pragma unroll
            for (int i = 0; i < 8; i++) {
                float di = eq - 2.0f * a[i];
                if (di < bv[i]) { bv[i] = di; bi[i] = code; }  // ascending: first min
            }
        }

        // ---- reduction: 64 candidates per token -> slice partial ----
        __syncthreads();
        float* rv = (float*)smem;             // [32][64] floats, reuses es0
        int*   ri = (int*)(smem + 8192);      // [32][64] ints
#pragma unroll
        for (int i = 0; i < 8; i++) {
            int tok = 8 * h + i;
            rv[tok * 64 + c] = bv[i];
            ri[tok * 64 + c] = bi[i];
        }
        __syncthreads();
        if (tid < 32 && grp * 32 + tid < nfix) {
            float V = CUDART_INF_F; int I = 0;
            for (int j = 0; j < 64; j++) {
                float v = rv[tid * 64 + j]; int id = ri[tid * 64 + j];
                if (v < V || (v == V && id < I)) { V = v; I = id; }
            }
            int slot = grp * 32 + tid;
            g_pv[slot * NSLICE + sl] = V;
            g_pi[slot * NSLICE + sl] = I;
        }
    }
}

// Fold the NSLICE slice partials per contested token (ascending slices =
// ascending code ranges; strict < keeps the lowest code -> first-min).
__global__ void k_fixmerge(float* __restrict__ out_idx) {
    int s = blockIdx.x * blockDim.x + threadIdx.x;
    if (s >= g_nfix) return;
    float V = g_pv[s * NSLICE]; int I = g_pi[s * NSLICE];
#pragma unroll
    for (int q = 1; q < NSLICE; q++) {
        float v = g_pv[s * NSLICE + q];
        if (v < V) { V = v; I = g_pi[s * NSLICE + q]; }
    }
    int token = g_fixlist[s];
    g_idx[token] = I;
    out_idx[token] = (float)I;
}

// ===========================================================================
// Fused counts/sum_embeddings scatter, z_q gather, commitment-loss partial.
// grid (NTOK/256, 4). e-rows for this 64-dim chunk staged in smem via
// coalesced cooperative loads.
// ===========================================================================
#define SMEM_SG (1024u + 256u * 65u * 4u)   // sidx + es[256][65]

__global__ void k_scatter_gather(const float* __restrict__ z,
                                 const float* __restrict__ emb,
                                 float* __restrict__ out_zq) {
    extern __shared__ __align__(16) char smg[];
    int* sidx = (int*)smg;
    float* es = (float*)(smg + 1024);

    int tid   = threadIdx.x;
    int lane  = tid & 31;
    int w     = tid >> 5;
    int tok0  = blockIdx.x * 256;
    int b     = tok0 >> 11;
    int tl    = (tok0 & 2047) + tid;
    int token = tok0 + tid;
    int idx   = g_idx[token];
    sidx[tid] = idx;
    if (blockIdx.y == 0) atomicAdd(&g_counts[idx], 1.0f);
    __syncthreads();

    int d0 = blockIdx.y * 64;
#pragma unroll
    for (int j = 0; j < 16; j++) {
        int ta  = w * 32 + 2 * j + (lane >> 4);
        int seg = lane & 15;
        float4 v = *(const float4*)(emb + (size_t)sidx[ta] * DIM + d0 + seg * 4);
        float* dst = es + ta * 65 + seg * 4;
        dst[0] = v.x; dst[1] = v.y; dst[2] = v.z; dst[3] = v.w;
    }
    __syncthreads();

    const float* zb = z + (size_t)b * DIM * TLEN;
    float*       ob = out_zq + (size_t)b * DIM * TLEN;
    float* sr = g_sumemb + (size_t)idx * DIM;
    const float* myrow = es + tid * 65;

    float lacc = 0.f;
#pragma unroll 8
    for (int dd = 0; dd < 64; dd++) {
        int d = d0 + dd;
        float zv = zb[(size_t)d * TLEN + tl];
        float ev = myrow[dd];
        ob[(size_t)d * TLEN + tl] = zv + (ev - zv);   // straight-through
        atomicAdd(sr + d, zv);
        float df = zv - ev;
        lacc = fmaf(df, df, lacc);
    }
#pragma unroll
    for (int o = 16; o; o >>= 1) lacc += __shfl_xor_sync(0xFFFFFFFFu, lacc, o);
    if (lane == 0) atomicAdd(&g_scal[0], lacc);
}

// ===========================================================================
// Single block: new_cluster_size, n, utilization, loss.
// ===========================================================================
__global__ void k_reduce(const float* __restrict__ cs,
                         float* __restrict__ out_ncs,
                         float* __restrict__ out_loss,
                         float* __restrict__ out_util) {
    __shared__ float sn[256];
    __shared__ float sz[256];
    int tid = threadIdx.x;
    const float om = (float)(1.0 - 0.99);
    float nsum = 0.f, nz = 0.f;
    for (int k = tid; k < K_CODES; k += 256) {
        float c   = g_counts[k];
        float ncs = cs[k] * 0.99f + om * c;
        out_ncs[k] = ncs;
        nsum += ncs;
        nz += (c > 0.f) ? 1.f : 0.f;
    }
    sn[tid] = nsum; sz[tid] = nz;
    __syncthreads();
    for (int s = 128; s; s >>= 1) {
        if (tid < s) { sn[tid] += sn[tid + s]; sz[tid] += sz[tid + s]; }
        __syncthreads();
    }
    if (tid == 0) {
        g_scal[1] = sn[0];
        *out_loss = 1.0f * (g_scal[0] / (float)(NTOK * DIM));
        *out_util = sz[0] / (float)K_CODES;
    }
}

// ===========================================================================
// Elementwise EMA update.
// ===========================================================================
__global__ void k_update(const float* __restrict__ cs,
                         const float* __restrict__ ea,
                         float* __restrict__ out_nemb,
                         float* __restrict__ out_nea) {
    int gid = blockIdx.x * blockDim.x + threadIdx.x;
    int k = gid >> 8;
    const float om = (float)(1.0 - 0.99);
    float n   = g_scal[1];
    float ncs = cs[k] * 0.99f + om * g_counts[k];
    float smoothed = (ncs + 1e-5f) / (n + (float)(K_CODES * 1e-5)) * n;
    float nav = ea[gid] * 0.99f + om * g_sumemb[gid];
    out_nea[gid]  = nav;
    out_nemb[gid] = nav / smoothed;
}

// ===========================================================================
extern "C" void kernel_launch(void* const* d_in, const int* in_sizes, int n_in,
                              void* d_out, int out_size) {
    const float* z   = (const float*)d_in[0];   // (16, 256, 2048)
    const float* emb = (const float*)d_in[1];   // (8192, 256)
    const float* cs  = (const float*)d_in[2];   // (8192,)
    const float* ea  = (const float*)d_in[3];   // (8192, 256)
    float* out = (float*)d_out;

    float* o_zq   = out + OFF_ZQ;
    float* o_idx  = out + OFF_IDX;
    float* o_loss = out + OFF_LOSS;
    float* o_nemb = out + OFF_NEMB;
    float* o_ncs  = out + OFF_NCS;
    float* o_nea  = out + OFF_NEA;
    float* o_util = out + OFF_UTIL;

    cudaFuncSetAttribute(k_argmin_mma,
                         cudaFuncAttributeMaxDynamicSharedMemorySize, SMEM_MMA);
    cudaFuncSetAttribute(k_rescore,
                         cudaFuncAttributeMaxDynamicSharedMemorySize, SMEM_RES);
    cudaFuncSetAttribute(k_scatter_gather,
                         cudaFuncAttributeMaxDynamicSharedMemorySize, SMEM_SG);

    k_init_esq_prep<<<1024, 256>>>(emb);                  // launch 1
    k_prep_z<<<2048, 256>>>(z);                           // launch 2
    k_argmin_mma<<<NTOK / 256, 256, SMEM_MMA>>>(o_idx);   // launch 3
    k_rescore<<<256, 256, SMEM_RES>>>(emb);               // launch 4
    k_fixmerge<<<NTOK / 256, 256>>>(o_idx);               // launch 5
    dim3 sg_grid(NTOK / 256, 4);
    k_scatter_gather<<<sg_grid, 256, SMEM_SG>>>(z, emb, o_zq);  // launch 6
    k_reduce<<<1, 256>>>(cs, o_ncs, o_loss, o_util);      // launch 7
    k_update<<<K_CODES * DIM / 256, 256>>>(cs, ea, o_nemb, o_nea);  // launch 8
}